// round 1
// baseline (speedup 1.0000x reference)
#include <cuda_runtime.h>
#include <math.h>

// Shapes (fixed for this problem)
#define BB 8
#define LL 144
#define DM 256
#define DI 512
#define DS 64
#define DTR 4
#define BL (BB*LL)          // 1152
#define NXZ (2*DI)          // 1024
#define NDBC (DTR + 2*DS)   // 132

// Scratch (device globals — no allocation allowed)
__device__ float g_xz[BL * NXZ];     // in-proj output: cols [0,512)=ix_pre, [512,1024)=z
__device__ float g_ixc[BL * DI];     // conv+silu output
__device__ float g_dbc[BL * NDBC];   // [dt_r(4) | Bm(64) | Cm(64)]
__device__ float g_delta[BL * DI];   // softplus(dt_r @ W_dt^T + b_dt)
__device__ float g_yg[BL * DI];      // gated scan output (y + Dp*ix) * silu(z)

// ---------------------------------------------------------------------------
// Generic NT GEMM: C[m,n] = sum_k A[m,k] * B[n,k]
// M fixed = 1152 (multiple of 64). N guarded. K multiple of 16, rows 16B-aligned.
// 64x64 tile, 256 threads, 4x4 register micro-tile.
// ---------------------------------------------------------------------------
__global__ void gemm_nt64(const float* __restrict__ A, const float* __restrict__ Bm,
                          float* __restrict__ C, int N, int K) {
    __shared__ float As[16][68];
    __shared__ float Bs[16][68];
    const int t = threadIdx.x;
    const int tx = t & 15, ty = t >> 4;
    const int mBase = blockIdx.y * 64;
    const int nBase = blockIdx.x * 64;
    const int ldRow = t >> 2;            // 0..63
    const int ldCol = (t & 3) << 2;      // 0,4,8,12

    float acc[4][4];
#pragma unroll
    for (int i = 0; i < 4; i++)
#pragma unroll
        for (int j = 0; j < 4; j++) acc[i][j] = 0.f;

    for (int k0 = 0; k0 < K; k0 += 16) {
        float4 av = *(const float4*)(A + (size_t)(mBase + ldRow) * K + k0 + ldCol);
        float4 bv = make_float4(0.f, 0.f, 0.f, 0.f);
        if (nBase + ldRow < N)
            bv = *(const float4*)(Bm + (size_t)(nBase + ldRow) * K + k0 + ldCol);
        As[ldCol + 0][ldRow] = av.x; As[ldCol + 1][ldRow] = av.y;
        As[ldCol + 2][ldRow] = av.z; As[ldCol + 3][ldRow] = av.w;
        Bs[ldCol + 0][ldRow] = bv.x; Bs[ldCol + 1][ldRow] = bv.y;
        Bs[ldCol + 2][ldRow] = bv.z; Bs[ldCol + 3][ldRow] = bv.w;
        __syncthreads();
#pragma unroll
        for (int k = 0; k < 16; k++) {
            float ra[4], rb[4];
#pragma unroll
            for (int i = 0; i < 4; i++) ra[i] = As[k][ty * 4 + i];
#pragma unroll
            for (int j = 0; j < 4; j++) rb[j] = Bs[k][tx * 4 + j];
#pragma unroll
            for (int i = 0; i < 4; i++)
#pragma unroll
                for (int j = 0; j < 4; j++)
                    acc[i][j] = fmaf(ra[i], rb[j], acc[i][j]);
        }
        __syncthreads();
    }
#pragma unroll
    for (int i = 0; i < 4; i++) {
        const int m = mBase + ty * 4 + i;
#pragma unroll
        for (int j = 0; j < 4; j++) {
            const int n = nBase + tx * 4 + j;
            if (n < N) C[(size_t)m * N + n] = acc[i][j];
        }
    }
}

// ---------------------------------------------------------------------------
// Depthwise conv (k=4, pad left 2 / right 1, cross-correlation) + bias + SiLU
// Reads ix_pre from g_xz cols [0,512), writes g_ixc.
// ---------------------------------------------------------------------------
__global__ void conv_silu_k(const float* __restrict__ conv_w,
                            const float* __restrict__ conv_b) {
    const int idx = blockIdx.x * blockDim.x + threadIdx.x;  // over BL*DI
    if (idx >= BL * DI) return;
    const int d = idx & (DI - 1);
    const int bl = idx >> 9;
    const int l = bl % LL;
    const int b = bl / LL;
    float acc = conv_b[d];
#pragma unroll
    for (int k = 0; k < 4; k++) {
        const int ll = l - 2 + k;
        if (ll >= 0 && ll < LL)
            acc = fmaf(conv_w[d * 4 + k], g_xz[(size_t)(b * LL + ll) * NXZ + d], acc);
    }
    g_ixc[idx] = acc / (1.f + __expf(-acc));   // silu
}

// ---------------------------------------------------------------------------
// delta = softplus(dt_r @ W_dt^T + b_dt)     (K = 4)
// ---------------------------------------------------------------------------
__global__ void delta_k(const float* __restrict__ W_dt,
                        const float* __restrict__ b_dt) {
    const int idx = blockIdx.x * blockDim.x + threadIdx.x;  // over BL*DI
    if (idx >= BL * DI) return;
    const int d = idx & (DI - 1);
    const int bl = idx >> 9;
    const float* dtr = g_dbc + (size_t)bl * NDBC;
    float x = b_dt[d];
#pragma unroll
    for (int r = 0; r < DTR; r++)
        x = fmaf(dtr[r], W_dt[d * DTR + r], x);
    // numerically stable softplus
    g_delta[idx] = fmaxf(x, 0.f) + log1pf(__expf(-fabsf(x)));
}

// ---------------------------------------------------------------------------
// Selective scan. One warp per (b, d); each lane owns states n=lane, n=lane+32.
// Per l: h = exp(delta*A)*h + delta*ix*B;  y = sum_n h*C;  then gate & write.
// 512 blocks x 256 threads (8 warps each).
// ---------------------------------------------------------------------------
__global__ void scan_k(const float* __restrict__ A_log,
                       const float* __restrict__ Dp) {
    const int warp = threadIdx.x >> 5;
    const int lane = threadIdx.x & 31;
    const int gid = blockIdx.x * 8 + warp;   // 0..4095 = b*512 + d
    const int b = gid >> 9;
    const int d = gid & (DI - 1);

    const float a0 = -expf(A_log[d * DS + lane]);
    const float a1 = -expf(A_log[d * DS + lane + 32]);
    const float dp = Dp[d];

    float h0 = 0.f, h1 = 0.f;
    for (int l = 0; l < LL; l++) {
        const int bl = b * LL + l;
        const float delta = g_delta[(size_t)bl * DI + d];
        const float ixv   = g_ixc[(size_t)bl * DI + d];
        const float* row  = g_dbc + (size_t)bl * NDBC;
        const float B0 = row[DTR + lane];
        const float B1 = row[DTR + lane + 32];
        const float C0 = row[DTR + DS + lane];
        const float C1 = row[DTR + DS + lane + 32];

        const float dA0 = __expf(delta * a0);
        const float dA1 = __expf(delta * a1);
        const float dbx = delta * ixv;
        h0 = fmaf(dA0, h0, dbx * B0);
        h1 = fmaf(dA1, h1, dbx * B1);

        float y = fmaf(h0, C0, h1 * C1);
#pragma unroll
        for (int off = 16; off; off >>= 1)
            y += __shfl_xor_sync(0xffffffffu, y, off);

        if (lane == 0) {
            const float yv = fmaf(dp, ixv, y);
            const float z  = g_xz[(size_t)bl * NXZ + DI + d];
            const float g  = z / (1.f + __expf(-z));   // silu(z)
            g_yg[(size_t)bl * DI + d] = yv * g;
        }
    }
}

// ---------------------------------------------------------------------------
extern "C" void kernel_launch(void* const* d_in, const int* in_sizes, int n_in,
                              void* d_out, int out_size) {
    const float* x      = (const float*)d_in[0];
    // d_in[1] = lastin (unused by reference forward)
    const float* W_in   = (const float*)d_in[2];
    const float* conv_w = (const float*)d_in[3];
    const float* conv_b = (const float*)d_in[4];
    const float* W_x    = (const float*)d_in[5];
    const float* W_dt   = (const float*)d_in[6];
    const float* b_dt   = (const float*)d_in[7];
    const float* A_log  = (const float*)d_in[8];
    const float* Dp     = (const float*)d_in[9];
    const float* W_out  = (const float*)d_in[10];
    float* out = (float*)d_out;

    float *p_xz, *p_ixc, *p_dbc, *p_yg;
    cudaGetSymbolAddress((void**)&p_xz,  g_xz);
    cudaGetSymbolAddress((void**)&p_ixc, g_ixc);
    cudaGetSymbolAddress((void**)&p_dbc, g_dbc);
    cudaGetSymbolAddress((void**)&p_yg,  g_yg);

    // 1. xz = x @ W_in^T          (1152 x 1024, K=256)
    gemm_nt64<<<dim3(NXZ / 64, BL / 64), 256>>>(x, W_in, p_xz, NXZ, DM);

    // 2. depthwise conv + bias + silu
    conv_silu_k<<<(BL * DI + 255) / 256, 256>>>(conv_w, conv_b);

    // 3. dBC = ixc @ W_x^T        (1152 x 132, K=512)
    gemm_nt64<<<dim3((NDBC + 63) / 64, BL / 64), 256>>>(p_ixc, W_x, p_dbc, NDBC, DI);

    // 4. delta = softplus(dt_r @ W_dt^T + b_dt)
    delta_k<<<(BL * DI + 255) / 256, 256>>>(W_dt, b_dt);

    // 5. selective scan + gate
    scan_k<<<BB * DI / 8, 256>>>(A_log, Dp);

    // 6. out = yg @ W_out^T       (1152 x 256, K=512)
    gemm_nt64<<<dim3(DM / 64, BL / 64), 256>>>(p_yg, W_out, out, DM, DI);
}